// round 2
// baseline (speedup 1.0000x reference)
#include <cuda_runtime.h>

#define NN   50000
#define EE   800000
#define DF   128
#define NCLS 3
#define MQ   10000

// Scratch (static device globals — no runtime allocation).
__device__ __align__(16) float g_A[(size_t)NN * DF];
__device__ __align__(16) float g_B[(size_t)NN * DF];
__device__ __align__(16) float g_C[(size_t)NN * DF];
__device__ __align__(16) float g_logits[(size_t)NN * NCLS];

// ---------------------------------------------------------------------------
// GEMM: H[r][n] = sum_k act(X[r][k]) * W[n][k] + b[n];  AGG = H (agg init)
// BM=128, BN=128 (full), BK=32; 256 threads; 8x8 thread tile.
// ---------------------------------------------------------------------------
template <bool RELU_IN>
__global__ void __launch_bounds__(256) gemm_kernel(
    const float* __restrict__ X, const float* __restrict__ W,
    const float* __restrict__ bias,
    float* __restrict__ H, float* __restrict__ AGG)
{
    __shared__ float Xs[32][128];   // Xs[k][m]
    __shared__ float Ws[32][128];   // Ws[k][n] = W[n][k_global]

    const int tid  = threadIdx.x;
    const int row0 = blockIdx.x * 128;
    const int tr   = tid >> 4;      // 0..15 -> rows tr*8..tr*8+7
    const int tc   = tid & 15;      // 0..15 -> cols tc*8..tc*8+7

    float acc[8][8] = {};

    for (int kb = 0; kb < DF; kb += 32) {
        // Load X tile (128 rows x 32 k), float4 per thread x4
        #pragma unroll
        for (int i = 0; i < 4; i++) {
            int idx = tid + i * 256;          // 0..1023
            int r   = idx >> 3;               // 0..127
            int c4  = idx & 7;                // 0..7
            int gr  = row0 + r;
            float4 v = make_float4(0.f, 0.f, 0.f, 0.f);
            if (gr < NN)
                v = *reinterpret_cast<const float4*>(X + (size_t)gr * DF + kb + c4 * 4);
            if (RELU_IN) {
                v.x = fmaxf(v.x, 0.f); v.y = fmaxf(v.y, 0.f);
                v.z = fmaxf(v.z, 0.f); v.w = fmaxf(v.w, 0.f);
            }
            Xs[c4 * 4 + 0][r] = v.x; Xs[c4 * 4 + 1][r] = v.y;
            Xs[c4 * 4 + 2][r] = v.z; Xs[c4 * 4 + 3][r] = v.w;
        }
        // Load W tile transposed: Ws[k][n] = W[n][kb+k]
        #pragma unroll
        for (int i = 0; i < 4; i++) {
            int idx = tid + i * 256;
            int n   = idx >> 3;               // 0..127
            int c4  = idx & 7;                // 0..7
            float4 v = *reinterpret_cast<const float4*>(W + (size_t)n * DF + kb + c4 * 4);
            Ws[c4 * 4 + 0][n] = v.x; Ws[c4 * 4 + 1][n] = v.y;
            Ws[c4 * 4 + 2][n] = v.z; Ws[c4 * 4 + 3][n] = v.w;
        }
        __syncthreads();

        #pragma unroll
        for (int k = 0; k < 32; k++) {
            float4 m0 = *reinterpret_cast<const float4*>(&Xs[k][tr * 8]);
            float4 m1 = *reinterpret_cast<const float4*>(&Xs[k][tr * 8 + 4]);
            float4 n0 = *reinterpret_cast<const float4*>(&Ws[k][tc * 8]);
            float4 n1 = *reinterpret_cast<const float4*>(&Ws[k][tc * 8 + 4]);
            float rm[8] = {m0.x, m0.y, m0.z, m0.w, m1.x, m1.y, m1.z, m1.w};
            float rn[8] = {n0.x, n0.y, n0.z, n0.w, n1.x, n1.y, n1.z, n1.w};
            #pragma unroll
            for (int i = 0; i < 8; i++)
                #pragma unroll
                for (int j = 0; j < 8; j++)
                    acc[i][j] += rm[i] * rn[j];
        }
        __syncthreads();
    }

    float bn[8];
    #pragma unroll
    for (int j = 0; j < 8; j++) bn[j] = bias[tc * 8 + j];

    #pragma unroll
    for (int i = 0; i < 8; i++) {
        int gr = row0 + tr * 8 + i;
        if (gr < NN) {
            #pragma unroll
            for (int j = 0; j < 8; j += 4) {
                float4 v;
                v.x = acc[i][j + 0] + bn[j + 0];
                v.y = acc[i][j + 1] + bn[j + 1];
                v.z = acc[i][j + 2] + bn[j + 2];
                v.w = acc[i][j + 3] + bn[j + 3];
                *reinterpret_cast<float4*>(H   + (size_t)gr * DF + tc * 8 + j) = v;
                *reinterpret_cast<float4*>(AGG + (size_t)gr * DF + tc * 8 + j) = v;
            }
        }
    }
}

// ---------------------------------------------------------------------------
// Scatter: AGG[dst] += H[src], one warp per edge, float4 per lane.
// Indices are int32 (JAX default x64-disabled downcasts int64 -> int32).
// ---------------------------------------------------------------------------
__device__ __forceinline__ void atomic_add_f4(float* p, float4 v)
{
#if defined(__CUDA_ARCH__) && (__CUDA_ARCH__ >= 900)
    atomicAdd(reinterpret_cast<float4*>(p), v);
#else
    atomicAdd(p + 0, v.x); atomicAdd(p + 1, v.y);
    atomicAdd(p + 2, v.z); atomicAdd(p + 3, v.w);
#endif
}

__global__ void __launch_bounds__(256) scatter_kernel(
    const float* __restrict__ H, float* __restrict__ AGG,
    const int* __restrict__ edges)
{
    const int warpId = (blockIdx.x * blockDim.x + threadIdx.x) >> 5;
    const int lane   = threadIdx.x & 31;
    const int nWarps = (gridDim.x * blockDim.x) >> 5;
    for (int e = warpId; e < EE; e += nWarps) {
        int src = edges[e];
        int dst = edges[EE + e];
        if ((unsigned)src >= NN || (unsigned)dst >= NN) continue;  // defensive
        float4 v = *reinterpret_cast<const float4*>(H + (size_t)src * DF + lane * 4);
        atomic_add_f4(AGG + (size_t)dst * DF + lane * 4, v);
    }
}

// ---------------------------------------------------------------------------
// Head: x_embed = relu(AGG); logits = x_embed @ Wout^T + bout; ypred = argmax.
// One warp per node.
// ---------------------------------------------------------------------------
__global__ void __launch_bounds__(256) final_kernel(
    const float* __restrict__ AGG, const float* __restrict__ Wout,
    const float* __restrict__ bout, float* __restrict__ out)
{
    const int warpId = (blockIdx.x * blockDim.x + threadIdx.x) >> 5;
    const int lane   = threadIdx.x & 31;
    if (warpId >= NN) return;

    float4 v = *reinterpret_cast<const float4*>(AGG + (size_t)warpId * DF + lane * 4);
    v.x = fmaxf(v.x, 0.f); v.y = fmaxf(v.y, 0.f);
    v.z = fmaxf(v.z, 0.f); v.w = fmaxf(v.w, 0.f);
    *reinterpret_cast<float4*>(out + (size_t)warpId * DF + lane * 4) = v;  // x_embed

    float l[NCLS];
    #pragma unroll
    for (int c = 0; c < NCLS; c++) {
        float4 w = *reinterpret_cast<const float4*>(Wout + (size_t)c * DF + lane * 4);
        l[c] = v.x * w.x + v.y * w.y + v.z * w.z + v.w * w.w;
    }
    #pragma unroll
    for (int off = 16; off > 0; off >>= 1) {
        l[0] += __shfl_xor_sync(0xffffffffu, l[0], off);
        l[1] += __shfl_xor_sync(0xffffffffu, l[1], off);
        l[2] += __shfl_xor_sync(0xffffffffu, l[2], off);
    }
    if (lane == 0) {
        l[0] += bout[0]; l[1] += bout[1]; l[2] += bout[2];
        g_logits[(size_t)warpId * 3 + 0] = l[0];
        g_logits[(size_t)warpId * 3 + 1] = l[1];
        g_logits[(size_t)warpId * 3 + 2] = l[2];
        int am = 0; float best = l[0];
        if (l[1] > best) { best = l[1]; am = 1; }
        if (l[2] > best) { best = l[2]; am = 2; }
        out[(size_t)NN * DF + (size_t)MQ * NCLS + warpId] = (float)am;  // ypred
    }
}

// node_output = logits[node_index]; y_nodepred = ypred[node_index]
__global__ void gather_kernel(const int* __restrict__ node_index,
                              float* __restrict__ out)
{
    int i = blockIdx.x * blockDim.x + threadIdx.x;
    if (i >= MQ) return;
    int n = node_index[i];
    if ((unsigned)n >= NN) n = 0;  // defensive
    size_t base = (size_t)NN * DF;
    out[base + (size_t)i * 3 + 0] = g_logits[(size_t)n * 3 + 0];
    out[base + (size_t)i * 3 + 1] = g_logits[(size_t)n * 3 + 1];
    out[base + (size_t)i * 3 + 2] = g_logits[(size_t)n * 3 + 2];
    out[base + (size_t)MQ * NCLS + NN + i] = out[base + (size_t)MQ * NCLS + n];
}

// ---------------------------------------------------------------------------
extern "C" void kernel_launch(void* const* d_in, const int* in_sizes, int n_in,
                              void* d_out, int out_size)
{
    const float* x          = (const float*)d_in[0];
    const int*   edges      = (const int*)d_in[1];       // int32 (JAX default)
    /* d_in[2] node_label: unused (zeros) */
    const int*   node_index = (const int*)d_in[3];       // int32 (JAX default)
    const float* W1 = (const float*)d_in[4];  const float* b1 = (const float*)d_in[5];
    const float* W2 = (const float*)d_in[6];  const float* b2 = (const float*)d_in[7];
    const float* W3 = (const float*)d_in[8];  const float* b3 = (const float*)d_in[9];
    const float* Wout = (const float*)d_in[10]; const float* bout = (const float*)d_in[11];
    float* out = (float*)d_out;

    float *A, *B, *C;
    cudaGetSymbolAddress((void**)&A, g_A);
    cudaGetSymbolAddress((void**)&B, g_B);
    cudaGetSymbolAddress((void**)&C, g_C);

    const int gemm_blocks = (NN + 127) / 128;   // 391
    const int scat_blocks = 8192;               // 65536 warps, ~12 edges each

    // Layer 1: input x (no relu on read)
    gemm_kernel<false><<<gemm_blocks, 256>>>(x, W1, b1, B, A);
    scatter_kernel<<<scat_blocks, 256>>>(B, A, edges);
    // Layer 2: relu(A) on read
    gemm_kernel<true><<<gemm_blocks, 256>>>(A, W2, b2, B, C);
    scatter_kernel<<<scat_blocks, 256>>>(B, C, edges);
    // Layer 3: relu(C) on read
    gemm_kernel<true><<<gemm_blocks, 256>>>(C, W3, b3, B, A);
    scatter_kernel<<<scat_blocks, 256>>>(B, A, edges);
    // Head
    final_kernel<<<((size_t)NN * 32 + 255) / 256, 256>>>(A, Wout, bout, out);
    gather_kernel<<<(MQ + 255) / 256, 256>>>(node_index, out);
}

// round 3
// speedup vs baseline: 1.1787x; 1.1787x over previous
#include <cuda_runtime.h>

#define NN   50000
#define EE   800000
#define DF   128
#define NCLS 3
#define MQ   10000

// Scratch (static device globals — no runtime allocation).
__device__ __align__(16) float g_H[(size_t)NN * DF];
__device__ __align__(16) float g_A[(size_t)NN * DF];
__device__ __align__(16) float g_logits[(size_t)NN * NCLS];
__device__ int g_deg[NN];
__device__ int g_off[NN];
__device__ int g_cur[NN];
__device__ int g_csr[EE];

// ---------------------------------------------------------------------------
// CSR build: zero degrees -> histogram(dst) -> exclusive scan -> fill src ids
// ---------------------------------------------------------------------------
__global__ void zero_deg_kernel()
{
    int i = blockIdx.x * blockDim.x + threadIdx.x;
    if (i < NN) g_deg[i] = 0;
}

__global__ void hist_kernel(const int* __restrict__ edges)
{
    int e = blockIdx.x * blockDim.x + threadIdx.x;
    if (e >= EE) return;
    int dst = edges[EE + e];
    if ((unsigned)dst < NN) atomicAdd(&g_deg[dst], 1);
}

__global__ void __launch_bounds__(1024) scan_kernel()
{
    __shared__ int sh[1024];
    const int T = 1024;
    const int CH = (NN + T - 1) / T;          // 49
    int t = threadIdx.x;
    int start = t * CH;
    int end   = min(start + CH, NN);

    int s = 0;
    for (int i = start; i < end; i++) s += g_deg[i];
    sh[t] = s;
    __syncthreads();

    // Hillis-Steele inclusive scan
    for (int off = 1; off < T; off <<= 1) {
        int v = (t >= off) ? sh[t - off] : 0;
        __syncthreads();
        sh[t] += v;
        __syncthreads();
    }
    int base = sh[t] - s;   // exclusive prefix for this thread's chunk

    int run = base;
    for (int i = start; i < end; i++) {
        g_off[i] = run;
        g_cur[i] = run;
        run += g_deg[i];
    }
}

__global__ void fill_kernel(const int* __restrict__ edges)
{
    int e = blockIdx.x * blockDim.x + threadIdx.x;
    if (e >= EE) return;
    int dst = edges[EE + e];
    int src = edges[e];
    if ((unsigned)dst >= NN || (unsigned)src >= NN) return;
    int p = atomicAdd(&g_cur[dst], 1);
    g_csr[p] = src;
}

// ---------------------------------------------------------------------------
// GEMM: H[r][n] = sum_k act(X[r][k]) * W[n][k] + b[n]
// BM=128, BN=128 (full), BK=32; 256 threads; 8x8 thread tile.
// ---------------------------------------------------------------------------
template <bool RELU_IN>
__global__ void __launch_bounds__(256) gemm_kernel(
    const float* __restrict__ X, const float* __restrict__ W,
    const float* __restrict__ bias, float* __restrict__ H)
{
    __shared__ float Xs[32][128];   // Xs[k][m]
    __shared__ float Ws[32][128];   // Ws[k][n] = W[n][k_global]

    const int tid  = threadIdx.x;
    const int row0 = blockIdx.x * 128;
    const int tr   = tid >> 4;
    const int tc   = tid & 15;

    float acc[8][8] = {};

    for (int kb = 0; kb < DF; kb += 32) {
        #pragma unroll
        for (int i = 0; i < 4; i++) {
            int idx = tid + i * 256;
            int r   = idx >> 3;
            int c4  = idx & 7;
            int gr  = row0 + r;
            float4 v = make_float4(0.f, 0.f, 0.f, 0.f);
            if (gr < NN)
                v = *reinterpret_cast<const float4*>(X + (size_t)gr * DF + kb + c4 * 4);
            if (RELU_IN) {
                v.x = fmaxf(v.x, 0.f); v.y = fmaxf(v.y, 0.f);
                v.z = fmaxf(v.z, 0.f); v.w = fmaxf(v.w, 0.f);
            }
            Xs[c4 * 4 + 0][r] = v.x; Xs[c4 * 4 + 1][r] = v.y;
            Xs[c4 * 4 + 2][r] = v.z; Xs[c4 * 4 + 3][r] = v.w;
        }
        #pragma unroll
        for (int i = 0; i < 4; i++) {
            int idx = tid + i * 256;
            int n   = idx >> 3;
            int c4  = idx & 7;
            float4 v = *reinterpret_cast<const float4*>(W + (size_t)n * DF + kb + c4 * 4);
            Ws[c4 * 4 + 0][n] = v.x; Ws[c4 * 4 + 1][n] = v.y;
            Ws[c4 * 4 + 2][n] = v.z; Ws[c4 * 4 + 3][n] = v.w;
        }
        __syncthreads();

        #pragma unroll
        for (int k = 0; k < 32; k++) {
            float4 m0 = *reinterpret_cast<const float4*>(&Xs[k][tr * 8]);
            float4 m1 = *reinterpret_cast<const float4*>(&Xs[k][tr * 8 + 4]);
            float4 n0 = *reinterpret_cast<const float4*>(&Ws[k][tc * 8]);
            float4 n1 = *reinterpret_cast<const float4*>(&Ws[k][tc * 8 + 4]);
            float rm[8] = {m0.x, m0.y, m0.z, m0.w, m1.x, m1.y, m1.z, m1.w};
            float rn[8] = {n0.x, n0.y, n0.z, n0.w, n1.x, n1.y, n1.z, n1.w};
            #pragma unroll
            for (int i = 0; i < 8; i++)
                #pragma unroll
                for (int j = 0; j < 8; j++)
                    acc[i][j] += rm[i] * rn[j];
        }
        __syncthreads();
    }

    float bn[8];
    #pragma unroll
    for (int j = 0; j < 8; j++) bn[j] = bias[tc * 8 + j];

    #pragma unroll
    for (int i = 0; i < 8; i++) {
        int gr = row0 + tr * 8 + i;
        if (gr < NN) {
            #pragma unroll
            for (int j = 0; j < 8; j += 4) {
                float4 v;
                v.x = acc[i][j + 0] + bn[j + 0];
                v.y = acc[i][j + 1] + bn[j + 1];
                v.z = acc[i][j + 2] + bn[j + 2];
                v.w = acc[i][j + 3] + bn[j + 3];
                *reinterpret_cast<float4*>(H + (size_t)gr * DF + tc * 8 + j) = v;
            }
        }
    }
}

// ---------------------------------------------------------------------------
// Gather segment-sum: AGG[n] = H[n] + sum_{s in csr[n]} H[s]. One warp/node.
// ---------------------------------------------------------------------------
__device__ __forceinline__ float4 gather_row(int node, int lane,
                                             const float* __restrict__ H)
{
    int start = g_off[node];
    int deg   = g_deg[node];

    float4 acc = *reinterpret_cast<const float4*>(H + (size_t)node * DF + lane * 4);

    for (int j = 0; j < deg; j += 32) {
        int rem  = deg - j;
        int cnt  = rem < 32 ? rem : 32;
        int myi  = (lane < cnt) ? g_csr[start + j + lane] : 0;
        #pragma unroll 4
        for (int k = 0; k < cnt; k++) {
            int s = __shfl_sync(0xffffffffu, myi, k);
            float4 v = *reinterpret_cast<const float4*>(H + (size_t)s * DF + lane * 4);
            acc.x += v.x; acc.y += v.y; acc.z += v.z; acc.w += v.w;
        }
    }
    return acc;
}

__global__ void __launch_bounds__(256) gather_kernel(
    const float* __restrict__ H, float* __restrict__ AGG)
{
    const int w    = (blockIdx.x * blockDim.x + threadIdx.x) >> 5;
    const int lane = threadIdx.x & 31;
    if (w >= NN) return;
    float4 acc = gather_row(w, lane, H);
    *reinterpret_cast<float4*>(AGG + (size_t)w * DF + lane * 4) = acc;
}

// Layer-3 gather fused with head: relu, x_embed, logits, argmax.
__global__ void __launch_bounds__(256) gather_head_kernel(
    const float* __restrict__ H, const float* __restrict__ Wout,
    const float* __restrict__ bout, float* __restrict__ out)
{
    const int w    = (blockIdx.x * blockDim.x + threadIdx.x) >> 5;
    const int lane = threadIdx.x & 31;
    if (w >= NN) return;

    float4 v = gather_row(w, lane, H);
    v.x = fmaxf(v.x, 0.f); v.y = fmaxf(v.y, 0.f);
    v.z = fmaxf(v.z, 0.f); v.w = fmaxf(v.w, 0.f);
    *reinterpret_cast<float4*>(out + (size_t)w * DF + lane * 4) = v;  // x_embed

    float l0, l1, l2;
    {
        float4 w0 = *reinterpret_cast<const float4*>(Wout + 0 * DF + lane * 4);
        float4 w1 = *reinterpret_cast<const float4*>(Wout + 1 * DF + lane * 4);
        float4 w2 = *reinterpret_cast<const float4*>(Wout + 2 * DF + lane * 4);
        l0 = v.x * w0.x + v.y * w0.y + v.z * w0.z + v.w * w0.w;
        l1 = v.x * w1.x + v.y * w1.y + v.z * w1.z + v.w * w1.w;
        l2 = v.x * w2.x + v.y * w2.y + v.z * w2.z + v.w * w2.w;
    }
    #pragma unroll
    for (int off = 16; off > 0; off >>= 1) {
        l0 += __shfl_xor_sync(0xffffffffu, l0, off);
        l1 += __shfl_xor_sync(0xffffffffu, l1, off);
        l2 += __shfl_xor_sync(0xffffffffu, l2, off);
    }
    if (lane == 0) {
        l0 += bout[0]; l1 += bout[1]; l2 += bout[2];
        g_logits[(size_t)w * 3 + 0] = l0;
        g_logits[(size_t)w * 3 + 1] = l1;
        g_logits[(size_t)w * 3 + 2] = l2;
        int am = 0; float best = l0;
        if (l1 > best) { best = l1; am = 1; }
        if (l2 > best) { best = l2; am = 2; }
        out[(size_t)NN * DF + (size_t)MQ * NCLS + w] = (float)am;  // ypred
    }
}

// node_output = logits[node_index]; y_nodepred = ypred[node_index]
__global__ void node_gather_kernel(const int* __restrict__ node_index,
                                   float* __restrict__ out)
{
    int i = blockIdx.x * blockDim.x + threadIdx.x;
    if (i >= MQ) return;
    int n = node_index[i];
    if ((unsigned)n >= NN) n = 0;
    size_t base = (size_t)NN * DF;
    out[base + (size_t)i * 3 + 0] = g_logits[(size_t)n * 3 + 0];
    out[base + (size_t)i * 3 + 1] = g_logits[(size_t)n * 3 + 1];
    out[base + (size_t)i * 3 + 2] = g_logits[(size_t)n * 3 + 2];
    out[base + (size_t)MQ * NCLS + NN + i] = out[base + (size_t)MQ * NCLS + n];
}

// ---------------------------------------------------------------------------
extern "C" void kernel_launch(void* const* d_in, const int* in_sizes, int n_in,
                              void* d_out, int out_size)
{
    const float* x          = (const float*)d_in[0];
    const int*   edges      = (const int*)d_in[1];
    /* d_in[2] node_label: unused (zeros) */
    const int*   node_index = (const int*)d_in[3];
    const float* W1 = (const float*)d_in[4];  const float* b1 = (const float*)d_in[5];
    const float* W2 = (const float*)d_in[6];  const float* b2 = (const float*)d_in[7];
    const float* W3 = (const float*)d_in[8];  const float* b3 = (const float*)d_in[9];
    const float* Wout = (const float*)d_in[10]; const float* bout = (const float*)d_in[11];
    float* out = (float*)d_out;

    float *H, *A;
    cudaGetSymbolAddress((void**)&H, g_H);
    cudaGetSymbolAddress((void**)&A, g_A);

    const int gemm_blocks = (NN + 127) / 128;          // 391
    const int edge_blocks = (EE + 255) / 256;          // 3125
    const int warp_blocks = ((size_t)NN * 32 + 255) / 256;  // 6250

    // CSR build (amortized over 3 layers)
    zero_deg_kernel<<<(NN + 255) / 256, 256>>>();
    hist_kernel<<<edge_blocks, 256>>>(edges);
    scan_kernel<<<1, 1024>>>();
    fill_kernel<<<edge_blocks, 256>>>(edges);

    // Layer 1
    gemm_kernel<false><<<gemm_blocks, 256>>>(x, W1, b1, H);
    gather_kernel<<<warp_blocks, 256>>>(H, A);
    // Layer 2 (relu on read)
    gemm_kernel<true><<<gemm_blocks, 256>>>(A, W2, b2, H);
    gather_kernel<<<warp_blocks, 256>>>(H, A);
    // Layer 3 + fused head
    gemm_kernel<true><<<gemm_blocks, 256>>>(A, W3, b3, H);
    gather_head_kernel<<<warp_blocks, 256>>>(H, Wout, bout, out);

    node_gather_kernel<<<(MQ + 255) / 256, 256>>>(node_index, out);
}